// round 16
// baseline (speedup 1.0000x reference)
#include <cuda_runtime.h>
#include <cuda_fp16.h>
#include <mma.h>
#include <math.h>
#include <stdint.h>

using namespace nvcuda;

// Problem constants
#define NTOK   16384      // B*S
#define DMODEL 1024
#define NHEAD  16
#define HD     64
#define NP     32
#define NR     8
#define NPR    256

// Scratch (allocation-free rule)
__device__ __half g_headsh[(size_t)NTOK * DMODEL];   // fp16 heads
__device__ __half g_Wh[(size_t)DMODEL * DMODEL];     // fp16 W_out [K,N]
__device__ float  g_biasrep[16 * DMODEL];            // bias replicated 16 rows

// ---------------------------------------------------------------------------
__device__ __forceinline__ uint32_t smem_u32(const void* p) {
    uint32_t a;
    asm("{ .reg .u64 t; cvta.to.shared.u64 t, %1; cvt.u32.u64 %0, t; }"
        : "=r"(a) : "l"(p));
    return a;
}
#define CP_ASYNC16(dst, src) \
    asm volatile("cp.async.cg.shared.global [%0], [%1], 16;" :: "r"(dst), "l"(src))
#define CP_COMMIT() asm volatile("cp.async.commit_group;" ::: "memory")
#define CP_WAIT1()  asm volatile("cp.async.wait_group 1;" ::: "memory")
#define CP_WAIT0()  asm volatile("cp.async.wait_group 0;" ::: "memory")

#define REDUX_MAX_U32(d, s, mask) \
    asm volatile("redux.sync.max.u32 %0, %1, %2;" : "=r"(d) : "r"(s), "r"(mask))

// order-preserving float<->uint mapping
__device__ __forceinline__ uint32_t f2ord(float f) {
    uint32_t b = __float_as_uint(f);
    return (b & 0x80000000u) ? ~b : (b | 0x80000000u);
}
__device__ __forceinline__ float ord2f(uint32_t u) {
    return __uint_as_float((u & 0x80000000u) ? (u & 0x7fffffffu) : ~u);
}

__device__ __forceinline__ float g8_sum(float v) {
#pragma unroll
    for (int o = 4; o > 0; o >>= 1) v += __shfl_xor_sync(0xffffffffu, v, o);
    return v;
}

// 5-level warp top-k helper: returns max (u0), 4th max (u4), 5th max (u5)
__device__ __forceinline__ void topk5(float lg, uint32_t& u0, uint32_t& u4,
                                      uint32_t& u5) {
    const uint32_t uo = f2ord(lg);
    uint32_t um;
    REDUX_MAX_U32(um, uo, 0xffffffffu);
    u0 = um;
    uint32_t cur = uo;
#pragma unroll
    for (int i = 0; i < 3; ++i) {
        cur = (cur == um) ? 0u : cur;
        REDUX_MAX_U32(um, cur, 0xffffffffu);
    }
    u4 = um;
    cur = (cur == um) ? 0u : cur;
    REDUX_MAX_U32(um, cur, 0xffffffffu);
    u5 = um;
}

// ---------------------------------------------------------------------------
// Attention kernel: one block = (head, 256-token set), 32 warps.
// R16 = R15 structure with the two scheduling fixes:
//  (1) Phase B split B1/B2 around ONE block barrier: B1 keeps (p_my, wv) for
//      4 tokens in registers (no Wm writes, no syncwarps); B2 batch-zeroes
//      the warp's 4 rows and scatters. Removes R15's per-token in-place
//      zero + 2 syncwarps.
//  (2) Phase A rebalanced: logits warps also compute 1 score tile (16 MMA)
//      vs score warps' 7 tiles (28 MMA) — was 12 vs 32.
// ---------------------------------------------------------------------------
#define ATTN_THREADS 1024
#define ATTN_WARPS   32
#define TOK_PER_BLK  256
#define CHUNK 128
#define KROWH 72          // padded x/V row in halfs (144B = 9 x 16B)
#define WHROW 40          // W_hi/W_lo row in halfs (80B = 5 x 16B)
#define LGROW 36          // logits row in floats (144B)
#define WMROW 264         // S / weight-matrix row in halfs (528B = 33 x 16B)
// float offsets (all *4 divisible by 16)
#define OFF_WHI  0                       // [64][40]h  = 1280 f
#define OFF_WLO  1280                    // [64][40]h  = 1280 f
#define OFF_KT   2560                    // [64][264]h = 8448 f  (K^T * 0.125)
#define OFF_VSH  11008                   // [256][72]h = 9216 f
#define OFF_XHI  20224                   // [128][72]h = 4608 f
#define OFF_XLO  24832                   // [128][72]h = 4608 f
#define OFF_LG   29440                   // [128][36]f = 4608 f
#define OFF_WM   34048                   // [128][264]h = 16896 f (S & Wm)
#define ATTN_SMEM_FLOATS 50944           // 203776 bytes

__global__ __launch_bounds__(ATTN_THREADS) void attn_kernel(
    const float* __restrict__ x,
    const float* __restrict__ Kst,
    const float* __restrict__ Vst,
    const float* __restrict__ Wrt)
{
    extern __shared__ float sm[];
    __half* Whi  = (__half*)(sm + OFF_WHI);
    __half* Wlo  = (__half*)(sm + OFF_WLO);
    __half* Kt   = (__half*)(sm + OFF_KT);
    __half* Vsh  = (__half*)(sm + OFF_VSH);
    __half* xhi  = (__half*)(sm + OFF_XHI);
    __half* xlo  = (__half*)(sm + OFF_XLO);
    float*  lg_s = sm + OFF_LG;
    __half* Wm   = (__half*)(sm + OFF_WM);   // scores in, weights out

    const int h    = blockIdx.x;
    const int tid  = threadIdx.x;
    const int wid  = tid >> 5;
    const int lane = tid & 31;
    const unsigned FULL = 0xffffffffu;

    // stage split router weights [d][p] -> hi/lo fp16, padded rows
    for (int i = tid; i < HD * NP; i += ATTN_THREADS) {
        const int d = i >> 5, p = i & 31;
        const float w = Wrt[h * HD * NP + i];
        const __half wh = __float2half_rn(w);
        Whi[d * WHROW + p] = wh;
        Wlo[d * WHROW + p] = __float2half_rn(w - __half2float(wh));
    }
    const float* Kh = Kst + (size_t)h * NPR * HD;
    const float* Vh = Vst + (size_t)h * NPR * HD;
    // Kt[d][pr] = K[pr][d] * 0.125 (scale folded); Vsh row-major
    for (int i = tid; i < NPR * HD; i += ATTN_THREADS) {
        const int pr = i >> 6, d = i & 63;
        Kt[d * WMROW + pr] = __float2half_rn(0.125f * Kh[i]);
    }
    for (int i = tid; i < NPR * HD / 2; i += ATTN_THREADS) {
        const int pr = i >> 5, d2 = i & 31;
        float2 vv = *(const float2*)(Vh + pr * HD + 2 * d2);
        ((__half2*)(Vsh + pr * KROWH))[d2] = __floats2half2_rn(vv.x, vv.y);
    }
    __syncthreads();

    const int e8 = lane >> 3;
    const int r8 = lane & 7;

    // fill decomposition: tok_local = tid>>3 (0..127), j = tid&7 (d-group)
    const int f_tok = tid >> 3;
    const int f_j   = tid & 7;

    // combine MMA tile ownership: 8 m-tiles x 4 n-tiles
    const int mTile = wid >> 2;
    const int nTile = wid & 3;

    const int blockbase = blockIdx.y * TOK_PER_BLK;

    for (int cc = 0; cc < TOK_PER_BLK / CHUNK; ++cc) {
        const int chunkbase = blockbase + cc * CHUNK;

        // ---- Phase F: stage x chunk as hi/lo fp16 pairs ----
        {
            const int tk = chunkbase + f_tok;
            const float4* gx = (const float4*)(x + (size_t)tk * DMODEL + h * HD);
            float4 v0 = gx[f_j * 2];
            float4 v1 = gx[f_j * 2 + 1];
            __half2 h0 = __floats2half2_rn(v0.x, v0.y);
            __half2 h1 = __floats2half2_rn(v0.z, v0.w);
            __half2 h2 = __floats2half2_rn(v1.x, v1.y);
            __half2 h3 = __floats2half2_rn(v1.z, v1.w);
            uint4 pk;
            pk.x = *(uint32_t*)&h0; pk.y = *(uint32_t*)&h1;
            pk.z = *(uint32_t*)&h2; pk.w = *(uint32_t*)&h3;
            *(uint4*)(xhi + f_tok * KROWH + 8 * f_j) = pk;

            float2 b0 = __half22float2(h0), b1 = __half22float2(h1);
            float2 b2 = __half22float2(h2), b3 = __half22float2(h3);
            __half2 l0 = __floats2half2_rn(v0.x - b0.x, v0.y - b0.y);
            __half2 l1 = __floats2half2_rn(v0.z - b1.x, v0.w - b1.y);
            __half2 l2 = __floats2half2_rn(v1.x - b2.x, v1.y - b2.y);
            __half2 l3 = __floats2half2_rn(v1.z - b3.x, v1.w - b3.y);
            uint4 pl;
            pl.x = *(uint32_t*)&l0; pl.y = *(uint32_t*)&l1;
            pl.z = *(uint32_t*)&l2; pl.w = *(uint32_t*)&l3;
            *(uint4*)(xlo + f_tok * KROWH + 8 * f_j) = pl;
        }
        __syncthreads();

        // ---- Phase A: logits MMA + 1 score tile (warps 0-15) ||
        //               7 score tiles (warps 16-31) ----
        // score tile helper: S[mT*16.., nn*16..] = xhi @ Kt (fp16 acc)
        auto score_tile = [&](int smT, int nn,
                              const wmma::fragment<wmma::matrix_a, 16, 16, 16,
                                                   half, wmma::row_major>* af) {
            wmma::fragment<wmma::accumulator, 16, 16, 16, half> acc;
            wmma::fill_fragment(acc, __float2half(0.0f));
#pragma unroll
            for (int k16 = 0; k16 < 4; ++k16) {
                wmma::fragment<wmma::matrix_b, 16, 16, 16, half,
                               wmma::row_major> bf;
                wmma::load_matrix_sync(bf,
                    Kt + (k16 * 16) * WMROW + nn * 16, WMROW);
                wmma::mma_sync(acc, af[k16], bf, acc);
            }
            wmma::store_matrix_sync(Wm + (smT * 16) * WMROW + nn * 16, acc,
                                    WMROW, wmma::mem_row_major);
        };

        if (wid < 16) {
            const int mT = wid >> 1;            // 0..7 token tile
            const int nT = wid & 1;             // 0..1 expert tile
            wmma::fragment<wmma::accumulator, 16, 16, 16, float> acc;
            wmma::fill_fragment(acc, 0.0f);
#pragma unroll
            for (int pass = 0; pass < 3; ++pass) {
                const __half* Asrc = (pass == 1) ? xlo : xhi;
                const __half* Bsrc = (pass == 2) ? Wlo : Whi;
#pragma unroll
                for (int k16 = 0; k16 < 4; ++k16) {
                    wmma::fragment<wmma::matrix_a, 16, 16, 16, half,
                                   wmma::row_major> af;
                    wmma::fragment<wmma::matrix_b, 16, 16, 16, half,
                                   wmma::row_major> bf;
                    wmma::load_matrix_sync(af,
                        Asrc + (mT * 16) * KROWH + k16 * 16, KROWH);
                    wmma::load_matrix_sync(bf,
                        Bsrc + (k16 * 16) * WHROW + nT * 16, WHROW);
                    wmma::mma_sync(acc, af, bf, acc);
                }
            }
            wmma::store_matrix_sync(lg_s + (mT * 16) * LGROW + nT * 16, acc,
                                    LGROW, wmma::mem_row_major);

            // one score tile: nn = 7 or 15 for this mT
            wmma::fragment<wmma::matrix_a, 16, 16, 16, half,
                           wmma::row_major> af[4];
#pragma unroll
            for (int k16 = 0; k16 < 4; ++k16)
                wmma::load_matrix_sync(af[k16],
                    xhi + (mT * 16) * KROWH + k16 * 16, KROWH);
            score_tile(mT, nT * 8 + 7, af);
        } else {
            // scores: 7 n-tiles per warp
            const int w2  = wid - 16;
            const int smT = w2 & 7;             // token tile 0..7
            const int snB = (w2 >> 3) * 8;      // n-tile base 0 or 8
            wmma::fragment<wmma::matrix_a, 16, 16, 16, half,
                           wmma::row_major> af[4];
#pragma unroll
            for (int k16 = 0; k16 < 4; ++k16)
                wmma::load_matrix_sync(af[k16],
                    xhi + (smT * 16) * KROWH + k16 * 16, KROWH);
#pragma unroll
            for (int nn = 0; nn < 7; ++nn)
                score_tile(smT, snB + nn, af);
        }
        __syncthreads();

        // ---- Phase B1: top-k (+exact fallback), gates, read S, softmax ----
        // results for the warp's 4 tokens held in registers
        int   pmy_r[4];
        float wv_r[4];
#pragma unroll
        for (int pass = 0; pass < 2; ++pass) {
            int   pa0[2], pa1[2], pa2[2], pa3[2];
            float ga_my[2];

#pragma unroll
            for (int u = 0; u < 2; ++u) {
                const int tok_local = 4 * wid + pass * 2 + u;
                float lg = lg_s[tok_local * LGROW + lane];

                uint32_t u0, u4, u5;
                topk5(lg, u0, u4, u5);

                // selection safety: if 4th/5th gap is tiny, recompute exact
                if (ord2f(u4) - ord2f(u5) < 1e-4f) {
                    const __half* xh = xhi + tok_local * KROWH;
                    const __half* xl = xlo + tok_local * KROWH;
                    float acc = 0.f;
#pragma unroll
                    for (int d = 0; d < HD; ++d) {
                        const float xv = __half2float(xh[d]) +
                                         __half2float(xl[d]);
                        const float wv = __half2float(Whi[d * WHROW + lane]) +
                                         __half2float(Wlo[d * WHROW + lane]);
                        acc = fmaf(xv, wv, acc);
                    }
                    lg = acc;
                    topk5(lg, u0, u4, u5);
                }

                const bool sel = (f2ord(lg) >= u4);
                unsigned b = __ballot_sync(FULL, sel);
                int q0 = __ffs(b) - 1; b &= b - 1;
                int q1 = __ffs(b) - 1; b &= b - 1;
                int q2 = __ffs(b) - 1; b &= b - 1;
                int q3 = __ffs(b) - 1;
                if (q0 < 0) q0 = 0;
                if (q1 < 0) q1 = q0;
                if (q2 < 0) q2 = q1;
                if (q3 < 0) q3 = q2;
                pa0[u] = q0; pa1[u] = q1; pa2[u] = q2; pa3[u] = q3;

                const float m0  = ord2f(u0);
                const float l0s = __shfl_sync(FULL, lg, q0);
                const float l1s = __shfl_sync(FULL, lg, q1);
                const float l2s = __shfl_sync(FULL, lg, q2);
                const float l3s = __shfl_sync(FULL, lg, q3);
                const float e0 = __expf(l0s - m0);
                const float e1 = __expf(l1s - m0);
                const float e2 = __expf(l2s - m0);
                const float e3 = __expf(l3s - m0);
                const float denom = (e0 + e1) + (e2 + e3);
                const float emy = (e8 == 0) ? e0 : (e8 == 1) ? e1
                                : (e8 == 2) ? e2 : e3;
                ga_my[u] = emy / denom;
            }

#pragma unroll
            for (int u = 0; u < 2; ++u) {
                const int tok_local = 4 * wid + pass * 2 + u;
                const int p_my = (e8 == 0) ? pa0[u] : (e8 == 1) ? pa1[u]
                               : (e8 == 2) ? pa2[u] : pa3[u];

                // read precomputed score (scaled by 1/8 already)
                const float sc =
                    __half2float(Wm[tok_local * WMROW + p_my * NR + r8]);

                // softmax over 8 slots (fp32)
                uint32_t um8;
                REDUX_MAX_U32(um8, f2ord(sc), 0xFFu << (8 * e8));
                const float sm8 = ord2f(um8);
                const float ex  = __expf(sc - sm8);
                const float wv  = (ex / g8_sum(ex)) * ga_my[u];

                pmy_r[pass * 2 + u] = p_my;
                wv_r[pass * 2 + u]  = wv;
            }
        }
        __syncthreads();   // ALL S reads complete before Wm overwrite

        // ---- Phase B2: batched zero of own rows + scatter ----
        {
            uint4 z; z.x = z.y = z.z = z.w = 0u;
#pragma unroll
            for (int t4 = 0; t4 < 4; ++t4) {
                uint4* rowz = (uint4*)(Wm + (4 * wid + t4) * WMROW);
                rowz[lane] = z;
                if (lane == 0) rowz[32] = z;
            }
            __syncwarp();
#pragma unroll
            for (int t4 = 0; t4 < 4; ++t4)
                Wm[(4 * wid + t4) * WMROW + pmy_r[t4] * NR + r8] =
                    __float2half_rn(wv_r[t4]);
        }
        __syncthreads();   // all rows are weights now

        // ---- Phase C: combine = Wm[128,256] @ Vsh[256,64] via WMMA ----
        wmma::fragment<wmma::accumulator, 16, 16, 16, float> cfr;
        wmma::fill_fragment(cfr, 0.0f);
#pragma unroll
        for (int k16 = 0; k16 < 16; ++k16) {
            wmma::fragment<wmma::matrix_a, 16, 16, 16, half,
                           wmma::row_major> af;
            wmma::fragment<wmma::matrix_b, 16, 16, 16, half,
                           wmma::row_major> bf;
            wmma::load_matrix_sync(af, Wm + (mTile * 16) * WMROW + k16 * 16,
                                   WMROW);
            wmma::load_matrix_sync(bf, Vsh + (k16 * 16) * KROWH + nTile * 16,
                                   KROWH);
            wmma::mma_sync(cfr, af, bf, cfr);
        }
        __syncthreads();   // all Wm reads done before staging overwrites it

        {
            float* stage = (float*)Wm + wid * 320;
            wmma::store_matrix_sync(stage, cfr, 20, wmma::mem_row_major);
            __syncwarp();

            const int row = lane >> 1;
            const int cp  = (lane & 1) * 8;
            const float4 v0 = *(const float4*)(stage + row * 20 + cp);
            const float4 v1 = *(const float4*)(stage + row * 20 + cp + 4);
            __half2 h0 = __floats2half2_rn(v0.x, v0.y);
            __half2 h1 = __floats2half2_rn(v0.z, v0.w);
            __half2 h2 = __floats2half2_rn(v1.x, v1.y);
            __half2 h3 = __floats2half2_rn(v1.z, v1.w);
            uint4 pk;
            pk.x = *(uint32_t*)&h0; pk.y = *(uint32_t*)&h1;
            pk.z = *(uint32_t*)&h2; pk.w = *(uint32_t*)&h3;
            const int tk = chunkbase + mTile * 16 + row;
            *(uint4*)(g_headsh + (size_t)tk * DMODEL + h * HD +
                      nTile * 16 + cp) = pk;
        }
        __syncthreads();   // buffers reused next chunk
    }
}

// ---------------------------------------------------------------------------
// Convert W_out -> fp16 and replicate bias into 16 rows
// ---------------------------------------------------------------------------
__global__ __launch_bounds__(256) void convert_kernel(
    const float* __restrict__ W, const float* __restrict__ bias)
{
    const int idx = blockIdx.x * 256 + threadIdx.x;           // float4 index
    const int n4 = DMODEL * DMODEL / 4;                       // 262144
    if (idx < n4) {
        float4 v = ((const float4*)W)[idx];
        __half2 h0 = __floats2half2_rn(v.x, v.y);
        __half2 h1 = __floats2half2_rn(v.z, v.w);
        ((__half2*)g_Wh)[idx * 2]     = h0;
        ((__half2*)g_Wh)[idx * 2 + 1] = h1;
    }
    if (idx < 16 * DMODEL / 4) {
        float4 b = ((const float4*)bias)[idx & (DMODEL / 4 - 1)];
        ((float4*)g_biasrep)[idx] = b;
    }
}

// ---------------------------------------------------------------------------
// GEMM: persistent CTAs, fp16 WMMA, fp32 accumulate (unchanged from R12)
// ---------------------------------------------------------------------------
#define GM 16384
#define GN 1024
#define GK 1024
#define BM 128
#define BN 128
#define BK 64
#define NKT (GK / BK)        // 16
#define NTILES ((GM / BM) * (GN / BN))   // 1024
#define STG 3
#define LDA_H 72
#define LDB_H 136
#define A_STG (BM * LDA_H)
#define B_STG (BK * LDB_H)
#define GEMM_SMEM ((STG * (A_STG + B_STG)) * 2)   // 107520 bytes

__global__ __launch_bounds__(128) void gemm_kernel(float* __restrict__ C)
{
    extern __shared__ __align__(16) __half smh[];
    const int tid = threadIdx.x;
    const int wid = tid >> 5;
    const int wm  = wid & 1;
    const int wn  = wid >> 1;

    const uint32_t smem_b = smem_u32(smh);

    const int ar = tid >> 3;
    const int ac = (tid & 7) * 8;
    const int br = tid >> 4;
    const int bc = (tid & 15) * 8;

    for (int t = blockIdx.x; t < NTILES; t += gridDim.x) {
        const int bm = (t >> 3) * BM;
        const int bn = (t & 7) * BN;
        const __half* Ag  = g_headsh + (size_t)bm * GK;
        const __half* Bgp = g_Wh + bn;

        wmma::fragment<wmma::accumulator, 16, 16, 16, float> cf[4][4];
#pragma unroll
        for (int i = 0; i < 4; ++i)
#pragma unroll
            for (int j = 0; j < 4; ++j)
                wmma::load_matrix_sync(cf[i][j],
                                       g_biasrep + bn + wn * 64 + j * 16,
                                       GN, wmma::mem_row_major);

        auto load_stage = [&](int kt, int s) {
            const int kof = kt * BK;
            uint32_t adst = smem_b + (s * A_STG) * 2;
            uint32_t bdst = smem_b + (STG * A_STG + s * B_STG) * 2;
#pragma unroll
            for (int i = 0; i < 8; ++i) {
                const int r = ar + i * 16;
                CP_ASYNC16(adst + (r * LDA_H + ac) * 2,
                           Ag + (size_t)r * GK + kof + ac);
            }
#pragma unroll
            for (int i = 0; i < 8; ++i) {
                const int r = br + i * 8;
                CP_ASYNC16(bdst + (r * LDB_H + bc) * 2,
                           Bgp + (size_t)(kof + r) * GN + bc);
            }
        };

        load_stage(0, 0); CP_COMMIT();
        load_stage(1, 1); CP_COMMIT();

        for (int c = 0; c < NKT; ++c) {
            const int s = c % 3;
            CP_WAIT1();
            __syncthreads();
            if (c + 2 < NKT) load_stage(c + 2, (c + 2) % 3);
            CP_COMMIT();

            const __half* As = smh + s * A_STG;
            const __half* Bs = smh + STG * A_STG + s * B_STG;
#pragma unroll
            for (int k0 = 0; k0 < BK; k0 += 16) {
                wmma::fragment<wmma::matrix_a, 16, 16, 16, half,
                               wmma::row_major> af[4];
                wmma::fragment<wmma::matrix_b, 16, 16, 16, half,
                               wmma::row_major> bf[4];
#pragma unroll
                for (int i = 0; i < 4; ++i)
                    wmma::load_matrix_sync(af[i],
                        As + (wm * 64 + i * 16) * LDA_H + k0, LDA_H);
#pragma unroll
                for (int j = 0; j < 4; ++j)
                    wmma::load_matrix_sync(bf[j],
                        Bs + k0 * LDB_H + wn * 64 + j * 16, LDB_H);
#pragma unroll
                for (int i = 0; i < 4; ++i)
#pragma unroll
                    for (int j = 0; j < 4; ++j)
                        wmma::mma_sync(cf[i][j], af[i], bf[j], cf[i][j]);
            }
        }

#pragma unroll
        for (int i = 0; i < 4; ++i)
#pragma unroll
            for (int j = 0; j < 4; ++j)
                wmma::store_matrix_sync(
                    C + (size_t)(bm + wm * 64 + i * 16) * GN + bn +
                        wn * 64 + j * 16,
                    cf[i][j], GN, wmma::mem_row_major);

        CP_WAIT0();
        __syncthreads();
    }
}

// ---------------------------------------------------------------------------
extern "C" void kernel_launch(void* const* d_in, const int* in_sizes, int n_in,
                              void* d_out, int out_size)
{
    const float* x    = (const float*)d_in[0];
    const float* Kst  = (const float*)d_in[1];
    const float* Vst  = (const float*)d_in[2];
    const float* Wrt  = (const float*)d_in[3];
    const float* Wout = (const float*)d_in[4];
    const float* bout = (const float*)d_in[5];
    float* out = (float*)d_out;

    const int attn_smem = ATTN_SMEM_FLOATS * (int)sizeof(float);   // 203776 B
    cudaFuncSetAttribute(attn_kernel,
                         cudaFuncAttributeMaxDynamicSharedMemorySize, attn_smem);
    cudaFuncSetAttribute(gemm_kernel,
                         cudaFuncAttributeMaxDynamicSharedMemorySize, GEMM_SMEM);

    int nsm = 148;
    cudaDeviceGetAttribute(&nsm, cudaDevAttrMultiProcessorCount, 0);

    attn_kernel<<<dim3(NHEAD, NTOK / TOK_PER_BLK), ATTN_THREADS, attn_smem>>>(
        x, Kst, Vst, Wrt);
    convert_kernel<<<DMODEL * DMODEL / 4 / 256, 256>>>(Wout, bout);
    gemm_kernel<<<2 * nsm, 128, GEMM_SMEM>>>(out);
}

// round 17
// speedup vs baseline: 1.0577x; 1.0577x over previous
#include <cuda_runtime.h>
#include <cuda_fp16.h>
#include <mma.h>
#include <math.h>
#include <stdint.h>

using namespace nvcuda;

// Problem constants
#define NTOK   16384      // B*S
#define DMODEL 1024
#define NHEAD  16
#define HD     64
#define NP     32
#define NR     8
#define NPR    256

// Scratch (allocation-free rule)
__device__ __half g_headsh[(size_t)NTOK * DMODEL];   // fp16 heads
__device__ __half g_Wh[(size_t)DMODEL * DMODEL];     // fp16 W_out [K,N]
__device__ float  g_biasrep[16 * DMODEL];            // bias replicated 16 rows

// ---------------------------------------------------------------------------
__device__ __forceinline__ uint32_t smem_u32(const void* p) {
    uint32_t a;
    asm("{ .reg .u64 t; cvta.to.shared.u64 t, %1; cvt.u32.u64 %0, t; }"
        : "=r"(a) : "l"(p));
    return a;
}
#define CP_ASYNC16(dst, src) \
    asm volatile("cp.async.cg.shared.global [%0], [%1], 16;" :: "r"(dst), "l"(src))
#define CP_COMMIT() asm volatile("cp.async.commit_group;" ::: "memory")
#define CP_WAIT1()  asm volatile("cp.async.wait_group 1;" ::: "memory")
#define CP_WAIT0()  asm volatile("cp.async.wait_group 0;" ::: "memory")

#define REDUX_MAX_U32(d, s, mask) \
    asm volatile("redux.sync.max.u32 %0, %1, %2;" : "=r"(d) : "r"(s), "r"(mask))

// order-preserving float<->uint mapping
__device__ __forceinline__ uint32_t f2ord(float f) {
    uint32_t b = __float_as_uint(f);
    return (b & 0x80000000u) ? ~b : (b | 0x80000000u);
}
__device__ __forceinline__ float ord2f(uint32_t u) {
    return __uint_as_float((u & 0x80000000u) ? (u & 0x7fffffffu) : ~u);
}

__device__ __forceinline__ float g8_sum(float v) {
#pragma unroll
    for (int o = 4; o > 0; o >>= 1) v += __shfl_xor_sync(0xffffffffu, v, o);
    return v;
}

// 5-level warp top-k helper: returns max (u0), 4th max (u4), 5th max (u5)
__device__ __forceinline__ void topk5(float lg, uint32_t& u0, uint32_t& u4,
                                      uint32_t& u5) {
    const uint32_t uo = f2ord(lg);
    uint32_t um;
    REDUX_MAX_U32(um, uo, 0xffffffffu);
    u0 = um;
    uint32_t cur = uo;
#pragma unroll
    for (int i = 0; i < 3; ++i) {
        cur = (cur == um) ? 0u : cur;
        REDUX_MAX_U32(um, cur, 0xffffffffu);
    }
    u4 = um;
    cur = (cur == um) ? 0u : cur;
    REDUX_MAX_U32(um, cur, 0xffffffffu);
    u5 = um;
}

// ---------------------------------------------------------------------------
// Attention kernel: one block = (head, 256-token set), 32 warps.
// R17 = R14 attention verbatim (the best-measured structure: split-fp16
// logits MMA on warps 0-15 || Wm zeroing on warps 16-31, per-token HFMA2
// score gather, tensorized combine), PLUS the W_out->fp16 conversion and
// bias replication folded into the prologue (each block converts 1/1024 of
// W; the former 6us convert_kernel is eliminated).
// ---------------------------------------------------------------------------
#define ATTN_THREADS 1024
#define ATTN_WARPS   32
#define TOK_PER_BLK  256
#define CHUNK 128
#define KROWH 72          // padded K/V/x row in halfs (144B = 9 x 16B)
#define WHROW 40          // W_hi/W_lo row in halfs (80B = 5 x 16B)
#define LGROW 36          // logits row in floats (144B) -- WMMA-legal
#define WMROW 264         // weight-matrix row in halfs (528B = 33 x 16B)
// float offsets
#define OFF_WHI  0                       // [64][40]h  = 1280 f
#define OFF_WLO  1280                    // [64][40]h  = 1280 f
#define OFF_KSH  2560                    // [256][72]h = 9216 f
#define OFF_VSH  11776                   // [256][72]h = 9216 f
#define OFF_XHI  20992                   // [128][72]h = 4608 f
#define OFF_XLO  25600                   // [128][72]h = 4608 f
#define OFF_LG   30208                   // [128][36]f = 4608 f
#define OFF_WM   34816                   // [128][264]h = 16896 f
#define ATTN_SMEM_FLOATS 51712           // 206848 bytes

__global__ __launch_bounds__(ATTN_THREADS) void attn_kernel(
    const float* __restrict__ x,
    const float* __restrict__ Kst,
    const float* __restrict__ Vst,
    const float* __restrict__ Wrt,
    const float* __restrict__ Wout,
    const float* __restrict__ bout)
{
    extern __shared__ float sm[];
    __half* Whi  = (__half*)(sm + OFF_WHI);
    __half* Wlo  = (__half*)(sm + OFF_WLO);
    __half* Ksh  = (__half*)(sm + OFF_KSH);
    __half* Vsh  = (__half*)(sm + OFF_VSH);
    __half* xhi  = (__half*)(sm + OFF_XHI);
    __half* xlo  = (__half*)(sm + OFF_XLO);
    float*  lg_s = sm + OFF_LG;
    __half* Wm   = (__half*)(sm + OFF_WM);

    const int h    = blockIdx.x;
    const int tid  = threadIdx.x;
    const int wid  = tid >> 5;
    const int lane = tid & 31;
    const unsigned FULL = 0xffffffffu;

    // ---- folded convert: this block converts its 1/1024 slice of W_out ----
    {
        const int bid = blockIdx.y * NHEAD + blockIdx.x;     // 0..1023
        if (tid < 256) {
            const int idx = bid * 256 + tid;                 // float4 index
            float4 v = ((const float4*)Wout)[idx];
            __half2 h0 = __floats2half2_rn(v.x, v.y);
            __half2 h1 = __floats2half2_rn(v.z, v.w);
            ((__half2*)g_Wh)[idx * 2]     = h0;
            ((__half2*)g_Wh)[idx * 2 + 1] = h1;
            if (bid < 16) {                                  // bias replicate
                const int bidx = bid * 256 + tid;            // 4096 float4
                float4 b = ((const float4*)bout)[bidx & (DMODEL / 4 - 1)];
                ((float4*)g_biasrep)[bidx] = b;
            }
        }
    }

    // stage split router weights [d][p] -> hi/lo fp16, padded rows
    for (int i = tid; i < HD * NP; i += ATTN_THREADS) {
        const int d = i >> 5, p = i & 31;
        const float w = Wrt[h * HD * NP + i];
        const __half wh = __float2half_rn(w);
        Whi[d * WHROW + p] = wh;
        Wlo[d * WHROW + p] = __float2half_rn(w - __half2float(wh));
    }
    const float* Kh = Kst + (size_t)h * NPR * HD;
    const float* Vh = Vst + (size_t)h * NPR * HD;
    for (int i = tid; i < NPR * HD / 2; i += ATTN_THREADS) {
        const int pr = i >> 5, d2 = i & 31;
        float2 kv = *(const float2*)(Kh + pr * HD + 2 * d2);
        ((__half2*)(Ksh + pr * KROWH))[d2] = __floats2half2_rn(kv.x, kv.y);
        float2 vv = *(const float2*)(Vh + pr * HD + 2 * d2);
        ((__half2*)(Vsh + pr * KROWH))[d2] = __floats2half2_rn(vv.x, vv.y);
    }
    __syncthreads();

    const int e8 = lane >> 3;
    const int r8 = lane & 7;

    // fill decomposition: tok_local = tid>>3 (0..127), j = tid&7 (d-group)
    const int f_tok = tid >> 3;
    const int f_j   = tid & 7;

    // combine MMA tile ownership: 8 m-tiles x 4 n-tiles
    const int mTile = wid >> 2;
    const int nTile = wid & 3;

    const int blockbase = blockIdx.y * TOK_PER_BLK;

    for (int cc = 0; cc < TOK_PER_BLK / CHUNK; ++cc) {
        const int chunkbase = blockbase + cc * CHUNK;

        // ---- Phase F: stage x chunk as hi/lo fp16 pairs ----
        {
            const int tk = chunkbase + f_tok;
            const float4* gx = (const float4*)(x + (size_t)tk * DMODEL + h * HD);
            float4 v0 = gx[f_j * 2];
            float4 v1 = gx[f_j * 2 + 1];
            __half2 h0 = __floats2half2_rn(v0.x, v0.y);
            __half2 h1 = __floats2half2_rn(v0.z, v0.w);
            __half2 h2 = __floats2half2_rn(v1.x, v1.y);
            __half2 h3 = __floats2half2_rn(v1.z, v1.w);
            uint4 pk;
            pk.x = *(uint32_t*)&h0; pk.y = *(uint32_t*)&h1;
            pk.z = *(uint32_t*)&h2; pk.w = *(uint32_t*)&h3;
            *(uint4*)(xhi + f_tok * KROWH + 8 * f_j) = pk;

            float2 b0 = __half22float2(h0), b1 = __half22float2(h1);
            float2 b2 = __half22float2(h2), b3 = __half22float2(h3);
            __half2 l0 = __floats2half2_rn(v0.x - b0.x, v0.y - b0.y);
            __half2 l1 = __floats2half2_rn(v0.z - b1.x, v0.w - b1.y);
            __half2 l2 = __floats2half2_rn(v1.x - b2.x, v1.y - b2.y);
            __half2 l3 = __floats2half2_rn(v1.z - b3.x, v1.w - b3.y);
            uint4 pl;
            pl.x = *(uint32_t*)&l0; pl.y = *(uint32_t*)&l1;
            pl.z = *(uint32_t*)&l2; pl.w = *(uint32_t*)&l3;
            *(uint4*)(xlo + f_tok * KROWH + 8 * f_j) = pl;
        }
        __syncthreads();

        // ---- Phase A: split-fp16 logits MMA (warps 0-15) || zero Wm ----
        if (wid < 16) {
            const int mT = wid >> 1;            // 0..7 token tile
            const int nT = wid & 1;             // 0..1 expert tile
            wmma::fragment<wmma::accumulator, 16, 16, 16, float> acc;
            wmma::fill_fragment(acc, 0.0f);
#pragma unroll
            for (int pass = 0; pass < 3; ++pass) {
                const __half* Asrc = (pass == 1) ? xlo : xhi;
                const __half* Bsrc = (pass == 2) ? Wlo : Whi;
#pragma unroll
                for (int k16 = 0; k16 < 4; ++k16) {
                    wmma::fragment<wmma::matrix_a, 16, 16, 16, half,
                                   wmma::row_major> af;
                    wmma::fragment<wmma::matrix_b, 16, 16, 16, half,
                                   wmma::row_major> bf;
                    wmma::load_matrix_sync(af,
                        Asrc + (mT * 16) * KROWH + k16 * 16, KROWH);
                    wmma::load_matrix_sync(bf,
                        Bsrc + (k16 * 16) * WHROW + nT * 16, WHROW);
                    wmma::mma_sync(acc, af, bf, acc);
                }
            }
            wmma::store_matrix_sync(lg_s + (mT * 16) * LGROW + nT * 16, acc,
                                    LGROW, wmma::mem_row_major);
        } else {
            // zero Wm: 128*264 halfs = 4224 uint4, 512 threads
            uint4 z; z.x = z.y = z.z = z.w = 0u;
            uint4* wz = (uint4*)Wm;
            const int t2 = tid - 512;
            for (int i = t2; i < CHUNK * WMROW / 8; i += 512)
                wz[i] = z;
        }
        __syncthreads();

        // ---- Phase B: top-k (+exact fallback) + scores + scatter ----
#pragma unroll
        for (int pass = 0; pass < 2; ++pass) {
            int   pa0[2], pa1[2], pa2[2], pa3[2];
            float ga_my[2];

#pragma unroll
            for (int u = 0; u < 2; ++u) {
                const int tok_local = 4 * wid + pass * 2 + u;
                float lg = lg_s[tok_local * LGROW + lane];

                uint32_t u0, u4, u5;
                topk5(lg, u0, u4, u5);

                // selection safety: if 4th/5th gap is tiny, recompute exact
                if (ord2f(u4) - ord2f(u5) < 1e-4f) {
                    const __half* xh = xhi + tok_local * KROWH;
                    const __half* xl = xlo + tok_local * KROWH;
                    float acc = 0.f;
#pragma unroll
                    for (int d = 0; d < HD; ++d) {
                        const float xv = __half2float(xh[d]) +
                                         __half2float(xl[d]);
                        const float wv = __half2float(Whi[d * WHROW + lane]) +
                                         __half2float(Wlo[d * WHROW + lane]);
                        acc = fmaf(xv, wv, acc);
                    }
                    lg = acc;
                    topk5(lg, u0, u4, u5);
                }

                const bool sel = (f2ord(lg) >= u4);
                unsigned b = __ballot_sync(FULL, sel);
                int q0 = __ffs(b) - 1; b &= b - 1;
                int q1 = __ffs(b) - 1; b &= b - 1;
                int q2 = __ffs(b) - 1; b &= b - 1;
                int q3 = __ffs(b) - 1;
                if (q0 < 0) q0 = 0;
                if (q1 < 0) q1 = q0;
                if (q2 < 0) q2 = q1;
                if (q3 < 0) q3 = q2;
                pa0[u] = q0; pa1[u] = q1; pa2[u] = q2; pa3[u] = q3;

                const float m0  = ord2f(u0);
                const float l0s = __shfl_sync(FULL, lg, q0);
                const float l1s = __shfl_sync(FULL, lg, q1);
                const float l2s = __shfl_sync(FULL, lg, q2);
                const float l3s = __shfl_sync(FULL, lg, q3);
                const float e0 = __expf(l0s - m0);
                const float e1 = __expf(l1s - m0);
                const float e2 = __expf(l2s - m0);
                const float e3 = __expf(l3s - m0);
                const float denom = (e0 + e1) + (e2 + e3);
                const float emy = (e8 == 0) ? e0 : (e8 == 1) ? e1
                                : (e8 == 2) ? e2 : e3;
                ga_my[u] = emy / denom;
            }

#pragma unroll
            for (int u = 0; u < 2; ++u) {
                const int tok_local = 4 * wid + pass * 2 + u;

                const int p_my = (e8 == 0) ? pa0[u] : (e8 == 1) ? pa1[u]
                               : (e8 == 2) ? pa2[u] : pa3[u];
                const float g_my = ga_my[u];

                // scores: fp16 HFMA2 on half2 x_hi and K
                const __half2* kr2 =
                    (const __half2*)(Ksh + (p_my * NR + r8) * KROWH);
                const __half2* xr2 =
                    (const __half2*)(xhi + tok_local * KROWH);
                __half2 ac0 = __float2half2_rn(0.f);
                __half2 ac1 = ac0, ac2 = ac0, ac3 = ac0;
#pragma unroll
                for (int q = 0; q < 8; ++q) {
                    const uint4 kk = *(const uint4*)(kr2 + q * 4);
                    const uint4 xx = *(const uint4*)(xr2 + q * 4);
                    ac0 = __hfma2(*(const __half2*)&xx.x,
                                  *(const __half2*)&kk.x, ac0);
                    ac1 = __hfma2(*(const __half2*)&xx.y,
                                  *(const __half2*)&kk.y, ac1);
                    ac2 = __hfma2(*(const __half2*)&xx.z,
                                  *(const __half2*)&kk.z, ac2);
                    ac3 = __hfma2(*(const __half2*)&xx.w,
                                  *(const __half2*)&kk.w, ac3);
                }
                const float2 f0 = __half22float2(__hadd2(ac0, ac1));
                const float2 f1 = __half22float2(__hadd2(ac2, ac3));
                float sc = ((f0.x + f0.y) + (f1.x + f1.y)) * 0.125f;

                uint32_t um8;
                REDUX_MAX_U32(um8, f2ord(sc), 0xFFu << (8 * e8));
                const float sm8 = ord2f(um8);
                const float ex  = __expf(sc - sm8);
                const float wv  = (ex / g8_sum(ex)) * g_my;

                Wm[tok_local * WMROW + p_my * NR + r8] = __float2half_rn(wv);
            }
        }
        __syncthreads();   // scatters + zero visible

        // ---- Phase C: combine = Wm[128,256] @ Vsh[256,64] via WMMA ----
        wmma::fragment<wmma::accumulator, 16, 16, 16, float> cfr;
        wmma::fill_fragment(cfr, 0.0f);
#pragma unroll
        for (int k16 = 0; k16 < 16; ++k16) {
            wmma::fragment<wmma::matrix_a, 16, 16, 16, half,
                           wmma::row_major> af;
            wmma::fragment<wmma::matrix_b, 16, 16, 16, half,
                           wmma::row_major> bf;
            wmma::load_matrix_sync(af, Wm + (mTile * 16) * WMROW + k16 * 16,
                                   WMROW);
            wmma::load_matrix_sync(bf, Vsh + (k16 * 16) * KROWH + nTile * 16,
                                   KROWH);
            wmma::mma_sync(cfr, af, bf, cfr);
        }
        __syncthreads();   // all Wm reads done before staging overwrites it

        {
            float* stage = (float*)Wm + wid * 320;
            wmma::store_matrix_sync(stage, cfr, 20, wmma::mem_row_major);
            __syncwarp();

            const int row = lane >> 1;
            const int cp  = (lane & 1) * 8;
            const float4 v0 = *(const float4*)(stage + row * 20 + cp);
            const float4 v1 = *(const float4*)(stage + row * 20 + cp + 4);
            __half2 h0 = __floats2half2_rn(v0.x, v0.y);
            __half2 h1 = __floats2half2_rn(v0.z, v0.w);
            __half2 h2 = __floats2half2_rn(v1.x, v1.y);
            __half2 h3 = __floats2half2_rn(v1.z, v1.w);
            uint4 pk;
            pk.x = *(uint32_t*)&h0; pk.y = *(uint32_t*)&h1;
            pk.z = *(uint32_t*)&h2; pk.w = *(uint32_t*)&h3;
            const int tk = chunkbase + mTile * 16 + row;
            *(uint4*)(g_headsh + (size_t)tk * DMODEL + h * HD +
                      nTile * 16 + cp) = pk;
        }
        __syncthreads();   // buffers reused next chunk
    }
}

// ---------------------------------------------------------------------------
// GEMM: persistent CTAs, fp16 WMMA, fp32 accumulate (unchanged from R12-R14)
// ---------------------------------------------------------------------------
#define GM 16384
#define GN 1024
#define GK 1024
#define BM 128
#define BN 128
#define BK 64
#define NKT (GK / BK)        // 16
#define NTILES ((GM / BM) * (GN / BN))   // 1024
#define STG 3
#define LDA_H 72
#define LDB_H 136
#define A_STG (BM * LDA_H)
#define B_STG (BK * LDB_H)
#define GEMM_SMEM ((STG * (A_STG + B_STG)) * 2)   // 107520 bytes

__global__ __launch_bounds__(128) void gemm_kernel(float* __restrict__ C)
{
    extern __shared__ __align__(16) __half smh[];
    const int tid = threadIdx.x;
    const int wid = tid >> 5;
    const int wm  = wid & 1;
    const int wn  = wid >> 1;

    const uint32_t smem_b = smem_u32(smh);

    const int ar = tid >> 3;
    const int ac = (tid & 7) * 8;
    const int br = tid >> 4;
    const int bc = (tid & 15) * 8;

    for (int t = blockIdx.x; t < NTILES; t += gridDim.x) {
        const int bm = (t >> 3) * BM;
        const int bn = (t & 7) * BN;
        const __half* Ag  = g_headsh + (size_t)bm * GK;
        const __half* Bgp = g_Wh + bn;

        wmma::fragment<wmma::accumulator, 16, 16, 16, float> cf[4][4];
#pragma unroll
        for (int i = 0; i < 4; ++i)
#pragma unroll
            for (int j = 0; j < 4; ++j)
                wmma::load_matrix_sync(cf[i][j],
                                       g_biasrep + bn + wn * 64 + j * 16,
                                       GN, wmma::mem_row_major);

        auto load_stage = [&](int kt, int s) {
            const int kof = kt * BK;
            uint32_t adst = smem_b + (s * A_STG) * 2;
            uint32_t bdst = smem_b + (STG * A_STG + s * B_STG) * 2;
#pragma unroll
            for (int i = 0; i < 8; ++i) {
                const int r = ar + i * 16;
                CP_ASYNC16(adst + (r * LDA_H + ac) * 2,
                           Ag + (size_t)r * GK + kof + ac);
            }
#pragma unroll
            for (int i = 0; i < 8; ++i) {
                const int r = br + i * 8;
                CP_ASYNC16(bdst + (r * LDB_H + bc) * 2,
                           Bgp + (size_t)(kof + r) * GN + bc);
            }
        };

        load_stage(0, 0); CP_COMMIT();
        load_stage(1, 1); CP_COMMIT();

        for (int c = 0; c < NKT; ++c) {
            const int s = c % 3;
            CP_WAIT1();
            __syncthreads();
            if (c + 2 < NKT) load_stage(c + 2, (c + 2) % 3);
            CP_COMMIT();

            const __half* As = smh + s * A_STG;
            const __half* Bs = smh + STG * A_STG + s * B_STG;
#pragma unroll
            for (int k0 = 0; k0 < BK; k0 += 16) {
                wmma::fragment<wmma::matrix_a, 16, 16, 16, half,
                               wmma::row_major> af[4];
                wmma::fragment<wmma::matrix_b, 16, 16, 16, half,
                               wmma::row_major> bf[4];
#pragma unroll
                for (int i = 0; i < 4; ++i)
                    wmma::load_matrix_sync(af[i],
                        As + (wm * 64 + i * 16) * LDA_H + k0, LDA_H);
#pragma unroll
                for (int j = 0; j < 4; ++j)
                    wmma::load_matrix_sync(bf[j],
                        Bs + k0 * LDB_H + wn * 64 + j * 16, LDB_H);
#pragma unroll
                for (int i = 0; i < 4; ++i)
#pragma unroll
                    for (int j = 0; j < 4; ++j)
                        wmma::mma_sync(cf[i][j], af[i], bf[j], cf[i][j]);
            }
        }

#pragma unroll
        for (int i = 0; i < 4; ++i)
#pragma unroll
            for (int j = 0; j < 4; ++j)
                wmma::store_matrix_sync(
                    C + (size_t)(bm + wm * 64 + i * 16) * GN + bn +
                        wn * 64 + j * 16,
                    cf[i][j], GN, wmma::mem_row_major);

        CP_WAIT0();
        __syncthreads();
    }
}

// ---------------------------------------------------------------------------
extern "C" void kernel_launch(void* const* d_in, const int* in_sizes, int n_in,
                              void* d_out, int out_size)
{
    const float* x    = (const float*)d_in[0];
    const float* Kst  = (const float*)d_in[1];
    const float* Vst  = (const float*)d_in[2];
    const float* Wrt  = (const float*)d_in[3];
    const float* Wout = (const float*)d_in[4];
    const float* bout = (const float*)d_in[5];
    float* out = (float*)d_out;

    const int attn_smem = ATTN_SMEM_FLOATS * (int)sizeof(float);   // 206848 B
    cudaFuncSetAttribute(attn_kernel,
                         cudaFuncAttributeMaxDynamicSharedMemorySize, attn_smem);
    cudaFuncSetAttribute(gemm_kernel,
                         cudaFuncAttributeMaxDynamicSharedMemorySize, GEMM_SMEM);

    int nsm = 148;
    cudaDeviceGetAttribute(&nsm, cudaDevAttrMultiProcessorCount, 0);

    attn_kernel<<<dim3(NHEAD, NTOK / TOK_PER_BLK), ATTN_THREADS, attn_smem>>>(
        x, Kst, Vst, Wrt, Wout, bout);
    gemm_kernel<<<2 * nsm, 128, GEMM_SMEM>>>(out);
}